// round 17
// baseline (speedup 1.0000x reference)
#include <cuda_runtime.h>

#define HH 512
#define WW 512
#define CHN 6
#define BATCH 2
#define EPS_F 1e-6f

__device__ __forceinline__ int refl(int i, int n) {
    if (i < 0) i = -i;
    if (i >= n) i = 2 * n - 2 - i;
    return i;
}

// upper-triangle (i<=j) linear index into 21-entry array
__device__ __forceinline__ constexpr int IU(int i, int j) {
    return i * 6 - i * (i - 1) / 2 + (j - i);
}
// lower-triangle (i>=j) linear index into 21-entry array
__device__ __forceinline__ constexpr int IL(int i, int j) {
    return i * (i + 1) / 2 + j;
}

// Horizontal window sum across lanes: returns w[l] = sum_{d=0..K-1} v[l+d].
// Valid for lanes l with l+K-1 <= 31 (we use l in [0,24)).
template <int K>
__device__ __forceinline__ float wtree(float v) {
    float s = v + __shfl_down_sync(0xffffffffu, v, 1);   // {0,1}
    s += __shfl_down_sync(0xffffffffu, s, 2);            // {0..3}
    if constexpr (K == 9) {
        s += __shfl_down_sync(0xffffffffu, s, 4);        // {0..7}
        s += __shfl_down_sync(0xffffffffu, v, 8);        // {0..8}
    } else {
        s += __shfl_down_sync(0xffffffffu, v, 4);        // {0..4}
    }
    return s;
}

// Per-pixel CCA from raw window sums (win layout: [0..5]=sx, [6..11]=sy,
// [12..32]=sxx upper-tri, [33..53]=syy upper-tri, [54..74]=sxy upper-tri).
__device__ __forceinline__ float cca6(const float* win, float inv_n) {
    const float* sx = win + 0;
    const float* sy = win + 6;
    const float* sxx = win + 12;
    const float* syy = win + 33;
    const float* sxyU = win + 54;

    float xm[6], ym[6];
#pragma unroll
    for (int i = 0; i < 6; i++) { xm[i] = sx[i] * inv_n; ym[i] = sy[i] * inv_n; }

    // Cholesky of cxx and cyy (lower L, 21 entries each); rsqrt-based.
    float Lx[21], Ly[21], ivx[6], ivy[6];
#pragma unroll
    for (int j = 0; j < 6; j++) {
        float dx = fmaf(-xm[j], xm[j], sxx[IU(j, j)] * inv_n) + EPS_F;
        float dy = fmaf(-ym[j], ym[j], syy[IU(j, j)] * inv_n) + EPS_F;
#pragma unroll
        for (int t = 0; t < j; t++) {
            dx = fmaf(-Lx[IL(j, t)], Lx[IL(j, t)], dx);
            dy = fmaf(-Ly[IL(j, t)], Ly[IL(j, t)], dy);
        }
        float rx = rsqrtf(dx), ry = rsqrtf(dy);
        ivx[j] = rx;
        ivy[j] = ry;
        Lx[IL(j, j)] = dx * rx;
        Ly[IL(j, j)] = dy * ry;
#pragma unroll
        for (int i = j + 1; i < 6; i++) {
            float vx = fmaf(-xm[j], xm[i], sxx[IU(j, i)] * inv_n);
            float vy = fmaf(-ym[j], ym[i], syy[IU(j, i)] * inv_n);
#pragma unroll
            for (int t = 0; t < j; t++) {
                vx = fmaf(-Lx[IL(i, t)], Lx[IL(j, t)], vx);
                vy = fmaf(-Ly[IL(i, t)], Ly[IL(j, t)], vy);
            }
            Lx[IL(i, j)] = vx * ivx[j];
            Ly[IL(i, j)] = vy * ivy[j];
        }
    }

    // M = Lx^{-1} * Cxy (upper triangle only).
    float MN[21];
#pragma unroll
    for (int j = 0; j < 6; j++) {
#pragma unroll
        for (int i = 0; i <= j; i++) {
            float v = fmaf(-xm[i], ym[j], sxyU[IU(i, j)] * inv_n);
#pragma unroll
            for (int t = 0; t < i; t++) v = fmaf(-Lx[IL(i, t)], MN[IU(t, j)], v);
            MN[IU(i, j)] = v * ivx[i];
        }
    }
    // N = M * Ly^{-1}, back-substitution per row.
    float sim = 0.f;
#pragma unroll
    for (int i = 0; i < 6; i++) {
#pragma unroll
        for (int j = 5; j >= i; j--) {
            float v = MN[IU(i, j)];
#pragma unroll
            for (int t = j + 1; t < 6; t++) v = fmaf(-MN[IU(i, t)], Ly[IL(t, j)], v);
            v *= ivy[j];
            MN[IU(i, j)] = v;
            if (j == i) sim += fabsf(v);
        }
    }
    return sim * (1.0f / 6.0f);
}

// Warp-separable body. lane = padded column of a 24-wide strip; each lane keeps
// the K-row vertical column-sums of all 75 moments in warp-private smem and
// slides them down one row at a time; horizontal K-window via shfl tree.
// NM = 75 moments. S = strip height (rows per warp).
template <int K, int S>
__device__ __forceinline__ void cca_body(
    const float* __restrict__ x, const float* __restrict__ y,
    float* __restrict__ out, int b, int ri, float* smcs) {
    constexpr int R = (K - 1) / 2;
    constexpr int NM = 75;
    constexpr float INV_N = 1.0f / (float)(K * K);

    const int lane = threadIdx.x & 31;
    const int wid = threadIdx.x >> 5;
    int txi = blockIdx.x * 24;
    if (txi > WW - 24) txi = WW - 24;   // overlapped edge tile (rewrites same values)
    const int ty0 = (blockIdx.y * 8 + wid) * S;
    const int gxl = refl(txi - R + lane, WW);

    float* cs = smcs + (wid * NM) * 32 + lane;   // [moment]*32 stride, lane contiguous

    const float* xb = x + (size_t)(b * CHN) * HH * WW + gxl;
    const float* yb = y + (size_t)(b * CHN) * HH * WW + gxl;

    float win[NM];

    // ---- init: accumulate K rows of products into regs, then STS + tree ----
    {
        float acc[NM];
#pragma unroll
        for (int m = 0; m < NM; m++) acc[m] = 0.f;
#pragma unroll 1
        for (int r = -R; r <= R; ++r) {
            int gy = refl(ty0 + r, HH);
            float xv[6], yv[6];
#pragma unroll
            for (int c = 0; c < 6; c++) {
                xv[c] = xb[(c * HH + gy) * WW];
                yv[c] = yb[(c * HH + gy) * WW];
            }
            int m = 0;
#pragma unroll
            for (int c = 0; c < 6; c++) { acc[m] += xv[c]; m++; }
#pragma unroll
            for (int c = 0; c < 6; c++) { acc[m] += yv[c]; m++; }
#pragma unroll
            for (int i = 0; i < 6; i++)
#pragma unroll
                for (int j = i; j < 6; j++) { acc[m] = fmaf(xv[i], xv[j], acc[m]); m++; }
#pragma unroll
            for (int i = 0; i < 6; i++)
#pragma unroll
                for (int j = i; j < 6; j++) { acc[m] = fmaf(yv[i], yv[j], acc[m]); m++; }
#pragma unroll
            for (int i = 0; i < 6; i++)
#pragma unroll
                for (int j = i; j < 6; j++) { acc[m] = fmaf(xv[i], yv[j], acc[m]); m++; }
        }
#pragma unroll
        for (int m = 0; m < NM; m++) {
            cs[m * 32] = acc[m];
            win[m] = wtree<K>(acc[m]);
        }
    }

    // row ty0 output
    {
        float sim = cca6(win, INV_N);
        if (lane < 24)
            out[(((size_t)b * HH + ty0) * WW + (txi + lane)) * 2 + ri] = sim;
    }

    // ---- remaining rows: slide colsums down, re-tree, cca ----
#pragma unroll 1
    for (int s = 1; s < S; ++s) {
        const int ty = ty0 + s;
        const int gyA = refl(ty + R, HH);
        const int gyS = refl(ty - R - 1, HH);
        float xa[6], ya[6], xs_[6], ys_[6];
#pragma unroll
        for (int c = 0; c < 6; c++) {
            xa[c] = xb[(c * HH + gyA) * WW];
            ya[c] = yb[(c * HH + gyA) * WW];
            xs_[c] = xb[(c * HH + gyS) * WW];
            ys_[c] = yb[(c * HH + gyS) * WW];
        }
        int m = 0;
#pragma unroll
        for (int c = 0; c < 6; c++) {
            float v = cs[m * 32] + (xa[c] - xs_[c]);
            cs[m * 32] = v;
            win[m] = wtree<K>(v);
            m++;
        }
#pragma unroll
        for (int c = 0; c < 6; c++) {
            float v = cs[m * 32] + (ya[c] - ys_[c]);
            cs[m * 32] = v;
            win[m] = wtree<K>(v);
            m++;
        }
#pragma unroll
        for (int i = 0; i < 6; i++)
#pragma unroll
            for (int j = i; j < 6; j++) {
                float v = fmaf(xa[i], xa[j], cs[m * 32]);
                v = fmaf(-xs_[i], xs_[j], v);
                cs[m * 32] = v;
                win[m] = wtree<K>(v);
                m++;
            }
#pragma unroll
        for (int i = 0; i < 6; i++)
#pragma unroll
            for (int j = i; j < 6; j++) {
                float v = fmaf(ya[i], ya[j], cs[m * 32]);
                v = fmaf(-ys_[i], ys_[j], v);
                cs[m * 32] = v;
                win[m] = wtree<K>(v);
                m++;
            }
#pragma unroll
        for (int i = 0; i < 6; i++)
#pragma unroll
            for (int j = i; j < 6; j++) {
                float v = fmaf(xa[i], ya[j], cs[m * 32]);
                v = fmaf(-xs_[i], ys_[j], v);
                cs[m * 32] = v;
                win[m] = wtree<K>(v);
                m++;
            }

        float sim = cca6(win, INV_N);
        if (lane < 24)
            out[(((size_t)b * HH + ty) * WW + (txi + lane)) * 2 + ri] = sim;
    }
}

// Single merged launch. z in {0,1}: K=9 (expensive, scheduled first);
// z in {2,3}: K=5. Warps are fully independent (no __syncthreads).
template <int S>
__global__ __launch_bounds__(256, 2) void cca_kernel(
    const float* __restrict__ x, const float* __restrict__ y,
    float* __restrict__ out) {
    extern __shared__ float smcs[];
    const int z = blockIdx.z;
    if (z < 2)
        cca_body<9, S>(x, y, out, z, 1, smcs);
    else
        cca_body<5, S>(x, y, out, z - 2, 0, smcs);
}

extern "C" void kernel_launch(void* const* d_in, const int* in_sizes, int n_in,
                              void* d_out, int out_size) {
    (void)in_sizes; (void)n_in; (void)out_size;
    const float* x = (const float*)d_in[0];
    const float* y = (const float*)d_in[1];
    float* out = (float*)d_out;

    constexpr int S = 8;              // rows per warp strip
    // x: 22 tiles of 24 cols (last overlaps); y: 512/(8 warps * S); z: 2 radii * 2 batches
    dim3 grid(22, HH / (8 * S), BATCH * 2);
    dim3 block(256);

    constexpr int SMEM = 8 * 75 * 32 * 4;   // 76.8 KB colsum buffer (8 warps)

    cudaFuncSetAttribute(cca_kernel<S>,
                         cudaFuncAttributeMaxDynamicSharedMemorySize, SMEM);

    cca_kernel<S><<<grid, block, SMEM>>>(x, y, out);
}